// round 5
// baseline (speedup 1.0000x reference)
#include <cuda_runtime.h>

namespace {

constexpr int Wd = 512;
constexpr int Hd = 512;
constexpr int TH = 8;             // output rows per CTA
constexpr int VW = 528;           // padded vbuf width (8 zero cols each side)
constexpr int NT = 256;
constexpr int WIN = TH + 14;      // 22-row input window

__device__ __forceinline__ unsigned long long pack2(float lo, float hi) {
    unsigned long long r;
    asm("mov.b64 %0, {%1, %2};" : "=l"(r) : "f"(lo), "f"(hi));
    return r;
}
__device__ __forceinline__ void fma2(unsigned long long& d,
                                     unsigned long long a,
                                     unsigned long long b) {
    asm("fma.rn.f32x2 %0, %1, %2, %0;" : "+l"(d) : "l"(a), "l"(b));
}
__host__ __device__ constexpr int widx(int j) { return j < 8 ? j : 14 - j; }

__global__ void __launch_bounds__(NT, 5)
gauss_kernel(const float* __restrict__ x, const float* __restrict__ sigma,
             float* __restrict__ out, int C)
{
    __shared__ float vbuf[TH * VW];   // 16896 B

    const int strip = blockIdx.x;
    const int ch    = blockIdx.y;
    const int b     = blockIdx.z;
    const int tid   = threadIdx.x;
    const int r0    = strip * TH;

    // ---- symmetric 1D Gaussian weights (8 distinct), packed broadcast ----
    const float sg  = sigma[b];
    const float inv = 1.0f / (2.0f * sg * sg + 1e-8f);
    float w[8];
    float s = 0.0f;
#pragma unroll
    for (int i = 0; i < 8; ++i) {
        const float a = (float)(7 - i);
        w[i] = __expf(-a * a * inv);
        s += (i < 7) ? 2.0f * w[i] : w[i];
    }
    const float rs = 1.0f / s;
    unsigned long long wp[8];
#pragma unroll
    for (int i = 0; i < 8; ++i) { w[i] *= rs; wp[i] = pack2(w[i], w[i]); }

    const size_t img = (size_t)(b * C + ch) * (Hd * Wd);
    const float* __restrict__ xp = x + img;
    float* __restrict__       op = out + img;

    // ---- zero-fill column halos (cols 0..7 and 520..527, 8 rows) ----
    if (tid < 32) {
        const int row = tid >> 2;
        const int q   = tid & 3;
        const int cc  = (q < 2) ? q * 4 : 520 + (q - 2) * 4;
        *reinterpret_cast<float4*>(&vbuf[row * VW + cc]) =
            make_float4(0.f, 0.f, 0.f, 0.f);
    }

    // ================= Stage 1: vertical, global -> vbuf =================
    // thread: 2 cols x 8 rows; 22-row sliding input window
    {
        const int c0 = tid * 2;
        const int rbase = r0 - 7;

        unsigned long long acc[TH];
#pragma unroll
        for (int o = 0; o < TH; ++o) acc[o] = 0ull;

        if (rbase >= 0 && rbase + WIN - 1 < Hd) {
            const float* p = xp + (size_t)rbase * Wd + c0;
#pragma unroll
            for (int rr = 0; rr < WIN; ++rr) {
                const unsigned long long v =
                    *reinterpret_cast<const unsigned long long*>(p + rr * Wd);
#pragma unroll
                for (int o = 0; o < TH; ++o) {
                    const int j = rr - o;
                    if (j >= 0 && j < 15) fma2(acc[o], v, wp[widx(j)]);
                }
            }
        } else {
            const float* colp = xp + c0;
#pragma unroll
            for (int rr = 0; rr < WIN; ++rr) {
                const int gr = rbase + rr;
                if ((unsigned)gr < (unsigned)Hd) {
                    const unsigned long long v =
                        *reinterpret_cast<const unsigned long long*>(
                            colp + (size_t)gr * Wd);
#pragma unroll
                    for (int o = 0; o < TH; ++o) {
                        const int j = rr - o;
                        if (j >= 0 && j < 15) fma2(acc[o], v, wp[widx(j)]);
                    }
                }
            }
        }
#pragma unroll
        for (int o = 0; o < TH; ++o)
            *reinterpret_cast<unsigned long long*>(&vbuf[o * VW + 8 + c0]) =
                acc[o];
    }
    __syncthreads();

    // ================= Stage 2: horizontal, vbuf -> global =================
    // thread: 4-col chunk x 4 rows; padded smem -> no column predicates
    {
        const int chunk = tid & 127;
        const int rsel  = tid >> 7;
        const int gc0   = chunk * 4;
        const float* basep = &vbuf[8 + gc0];

#pragma unroll
        for (int t = 0; t < 4; ++t) {
            const int row = rsel + 2 * t;
            const float* rp = basep + row * VW;

            float f[20];
            const float4 v0 = *reinterpret_cast<const float4*>(rp - 8);
            const float4 v1 = *reinterpret_cast<const float4*>(rp - 4);
            const float4 v2 = *reinterpret_cast<const float4*>(rp);
            const float4 v3 = *reinterpret_cast<const float4*>(rp + 4);
            const float4 v4 = *reinterpret_cast<const float4*>(rp + 8);
            f[0]=v0.x; f[1]=v0.y; f[2]=v0.z; f[3]=v0.w;
            f[4]=v1.x; f[5]=v1.y; f[6]=v1.z; f[7]=v1.w;
            f[8]=v2.x; f[9]=v2.y; f[10]=v2.z; f[11]=v2.w;
            f[12]=v3.x; f[13]=v3.y; f[14]=v3.z; f[15]=v3.w;
            f[16]=v4.x; f[17]=v4.y; f[18]=v4.z; f[19]=v4.w;

            unsigned long long ap0 = 0ull, ap1 = 0ull;
#pragma unroll
            for (int sidx = 1; sidx <= 17; ++sidx) {
                const unsigned long long P = pack2(f[sidx], f[sidx + 1]);
                if (sidx <= 15) fma2(ap0, P, wp[widx(sidx - 1)]);
                if (sidx >= 3)  fma2(ap1, P, wp[widx(sidx - 3)]);
            }
            *reinterpret_cast<ulonglong2*>(op + (size_t)(r0 + row) * Wd + gc0) =
                make_ulonglong2(ap0, ap1);
        }
    }
}

}  // namespace

extern "C" void kernel_launch(void* const* d_in, const int* in_sizes, int n_in,
                              void* d_out, int out_size) {
    const float* x     = (const float*)d_in[0];
    const float* sigma = (const float*)d_in[1];
    float* out         = (float*)d_out;

    const int B = in_sizes[1];                      // 32
    const int C = in_sizes[0] / (B * Hd * Wd);      // 3

    dim3 grid(Hd / TH, C, B);                       // 64 x 3 x 32 = 6144
    gauss_kernel<<<grid, NT>>>(x, sigma, out, C);
}